// round 1
// baseline (speedup 1.0000x reference)
#include <cuda_runtime.h>
#include <math.h>
#include <math_constants.h>

#define Bn   8
#define Tn   128
#define U1n  33
#define Dn   512
#define Vn   4096
#define ROWS (Bn*Tn*U1n)   // 33792

#define BM 128
#define BN 64
#define BK 32

// Scratch: per-row statistics from the fused GEMM pass.
__device__ float g_lse[ROWS];
__device__ float g_blank[ROWS];
__device__ float g_tgt[ROWS];
__device__ float g_sum[ROWS];

// ---------------------------------------------------------------------------
// Kernel 1: fused logits GEMM + online logsumexp + pick blank/target + row sum
// grid = ROWS/BM = 264 blocks, 256 threads.
// Thread (ty,tx): ty=tid/16 owns 8 rows, tx=tid%16 owns 4 V-columns of chunk.
// ---------------------------------------------------------------------------
__global__ void __launch_bounds__(256) fused_gemm_stats(
    const float* __restrict__ x, const float* __restrict__ w,
    const float* __restrict__ bias, const int* __restrict__ targets)
{
    __shared__ __align__(16) float As[BK][BM + 4];  // transposed, padded
    __shared__ __align__(16) float Bs[BK][BN + 4];

    const int tid  = threadIdx.x;
    const int ty   = tid >> 4;      // 0..15
    const int tx   = tid & 15;      // 0..15
    const int row0 = blockIdx.x * BM;

    // per-row target vocab index (only lanes share per-ty rows; cheap redundancy)
    int vt8[8];
#pragma unroll
    for (int i = 0; i < 8; i++) {
        int r = row0 + ty * 8 + i;
        int u = r % U1n;
        int b = r / (Tn * U1n);
        vt8[i] = (u < U1n - 1) ? targets[b * (U1n - 1) + u] : -1;
    }

    float m_run[8], s_run[8], rowsum[8];
#pragma unroll
    for (int i = 0; i < 8; i++) { m_run[i] = -CUDART_INF_F; s_run[i] = 0.f; rowsum[i] = 0.f; }

    for (int vc = 0; vc < Vn; vc += BN) {
        float acc[8][4];
#pragma unroll
        for (int i = 0; i < 8; i++)
#pragma unroll
            for (int j = 0; j < 4; j++) acc[i][j] = 0.f;

        for (int k0 = 0; k0 < Dn; k0 += BK) {
            __syncthreads();
            // load x tile (128 rows x 32 k) -> As[k][row]
#pragma unroll
            for (int jj = 0; jj < 4; jj++) {
                int idx = tid + jj * 256;        // 0..1023
                int r   = idx >> 3;
                int c4  = idx & 7;
                float4 v = *reinterpret_cast<const float4*>(
                    x + (size_t)(row0 + r) * Dn + k0 + c4 * 4);
                As[c4 * 4 + 0][r] = v.x; As[c4 * 4 + 1][r] = v.y;
                As[c4 * 4 + 2][r] = v.z; As[c4 * 4 + 3][r] = v.w;
            }
            // load W tile (64 vocab rows x 32 k) -> Bs[k][col]
#pragma unroll
            for (int jj = 0; jj < 2; jj++) {
                int idx = tid + jj * 256;        // 0..511
                int r   = idx >> 3;
                int c4  = idx & 7;
                float4 v = *reinterpret_cast<const float4*>(
                    w + (size_t)(vc + r) * Dn + k0 + c4 * 4);
                Bs[c4 * 4 + 0][r] = v.x; Bs[c4 * 4 + 1][r] = v.y;
                Bs[c4 * 4 + 2][r] = v.z; Bs[c4 * 4 + 3][r] = v.w;
            }
            __syncthreads();
#pragma unroll
            for (int k = 0; k < BK; k++) {
                float4 a0 = *reinterpret_cast<const float4*>(&As[k][ty * 8]);
                float4 a1 = *reinterpret_cast<const float4*>(&As[k][ty * 8 + 4]);
                float4 b0 = *reinterpret_cast<const float4*>(&Bs[k][tx * 4]);
                float a[8] = {a0.x, a0.y, a0.z, a0.w, a1.x, a1.y, a1.z, a1.w};
                float bv[4] = {b0.x, b0.y, b0.z, b0.w};
#pragma unroll
                for (int i = 0; i < 8; i++)
#pragma unroll
                    for (int j = 0; j < 4; j++)
                        acc[i][j] = fmaf(a[i], bv[j], acc[i][j]);
            }
        }

        // bias + per-chunk statistics (online LSE over V)
        float bb0 = bias[vc + tx * 4 + 0];
        float bb1 = bias[vc + tx * 4 + 1];
        float bb2 = bias[vc + tx * 4 + 2];
        float bb3 = bias[vc + tx * 4 + 3];
#pragma unroll
        for (int i = 0; i < 8; i++) {
            float l0 = acc[i][0] + bb0, l1 = acc[i][1] + bb1;
            float l2 = acc[i][2] + bb2, l3 = acc[i][3] + bb3;
            int grow = row0 + ty * 8 + i;
            if (vc == 0 && tx == 0) g_blank[grow] = l0;   // vocab 0 = BLANK
            int lv = vt8[i] - vc - tx * 4;
            if (lv >= 0 && lv < 4) {
                float lt = (lv == 0) ? l0 : (lv == 1) ? l1 : (lv == 2) ? l2 : l3;
                g_tgt[grow] = lt;
            }
            rowsum[i] += (l0 + l1) + (l2 + l3);
            float m4 = fmaxf(fmaxf(l0, l1), fmaxf(l2, l3));
#pragma unroll
            for (int o = 8; o > 0; o >>= 1)
                m4 = fmaxf(m4, __shfl_xor_sync(0xffffffffu, m4, o, 16));
            float e = __expf(l0 - m4) + __expf(l1 - m4) + __expf(l2 - m4) + __expf(l3 - m4);
#pragma unroll
            for (int o = 8; o > 0; o >>= 1)
                e += __shfl_xor_sync(0xffffffffu, e, o, 16);
            float mnew = fmaxf(m_run[i], m4);
            s_run[i] = s_run[i] * __expf(m_run[i] - mnew) + e * __expf(m4 - mnew);
            m_run[i] = mnew;
        }
    }

#pragma unroll
    for (int i = 0; i < 8; i++) {
        float rs = rowsum[i];
#pragma unroll
        for (int o = 8; o > 0; o >>= 1)
            rs += __shfl_xor_sync(0xffffffffu, rs, o, 16);
        if (tx == 0) {
            int grow = row0 + ty * 8 + i;
            g_sum[grow] = rs;
            g_lse[grow] = m_run[i] + logf(s_run[i]);
        }
    }
}

// ---------------------------------------------------------------------------
// Kernel 2: RNN-T wavefront DP (warp per batch, lane = u) + label-smoothed CE
// ---------------------------------------------------------------------------
__device__ __forceinline__ float laddexp(float a, float b) {
    float m = fmaxf(a, b);
    return m + log1pf(__expf(-fabsf(a - b)));
}

__global__ void __launch_bounds__(256) finalize_kernel(
    const int* __restrict__ targets,
    const int* __restrict__ src_lengths,
    const int* __restrict__ tgt_lengths,
    float* __restrict__ out)
{
    __shared__ float red[256];
    __shared__ float batch_loss[8];
    const int tid  = threadIdx.x;
    const int warp = tid >> 5, lane = tid & 31;

    // ---- RNN-T forward DP on anti-diagonals ----
    {
        int b  = warp;                       // 8 warps, one per batch
        int S  = src_lengths[b];
        int TG = tgt_lengths[b];
        int base = b * Tn * U1n;
        float cur = 0.f;                     // alpha[t][u] for u = lane
        float cur2 = 0.f;                    // alpha[t][32] (lane 31 only)
        float afin = 0.f;
        bool have = false;
        int nsteps = (S - 1) + 32;
        for (int s = 0; s <= nsteps; s++) {
            float left   = __shfl_up_sync(0xffffffffu, cur, 1);  // alpha[t][u-1]
            float prev31 = cur;              // lane31: alpha[s-32][31]
            int t = s - lane;
            if (t >= 0 && t <= S - 1) {
                int u = lane;
                if (t == 0) {
                    if (u == 0) cur = 0.f;
                    else {
                        int rE = base + (u - 1);
                        cur = left + (g_tgt[rE] - g_lse[rE]);
                    }
                } else {
                    int rB = base + (t - 1) * U1n + u;
                    float up = cur + (g_blank[rB] - g_lse[rB]);
                    if (u == 0) cur = up;
                    else {
                        int rE = base + t * U1n + (u - 1);
                        cur = laddexp(up, left + (g_tgt[rE] - g_lse[rE]));
                    }
                }
                if (t == S - 1 && u == TG) { afin = cur; have = true; }
            }
            if (lane == 31) {                // extra column u = 32
                int t2 = s - 32;
                if (t2 >= 0 && t2 <= S - 1) {
                    int rE = base + t2 * U1n + 31;
                    float lft = prev31 + (g_tgt[rE] - g_lse[rE]);
                    if (t2 == 0) cur2 = lft;
                    else {
                        int rB = base + (t2 - 1) * U1n + 32;
                        cur2 = laddexp(cur2 + (g_blank[rB] - g_lse[rB]), lft);
                    }
                    if (t2 == S - 1 && TG == 32) { afin = cur2; have = true; }
                }
            }
        }
        float lossb = 0.f;
        if (have) {
            int rB = base + (S - 1) * U1n + TG;
            lossb = -(afin + (g_blank[rB] - g_lse[rB]));
        }
#pragma unroll
        for (int o = 16; o > 0; o >>= 1)
            lossb += __shfl_xor_sync(0xffffffffu, lossb, o);
        if (lane == 0) batch_loss[b] = lossb;
    }
    __syncthreads();

    // ---- label-smoothed CE at t = src_len-1, u = 0..31 ----
    float term;
    {
        int b = tid >> 5;
        int u = tid & 31;
        int S = src_lengths[b];
        int tv = targets[b * 32 + u];
        int row = b * Tn * U1n + (S - 1) * U1n + u;
        float lse = g_lse[row];
        float nll = lse - g_tgt[row];
        float smooth = (float)Vn * lse - g_sum[row];
        const float LS  = 0.1f;
        const float eps = LS / (float)(Vn - 1);
        float m = (tv != 1) ? 1.f : 0.f;   // PAD = 1
        term = ((1.f - LS - eps) * nll + eps * smooth) * m;
    }
    red[tid] = term;
    __syncthreads();
#pragma unroll
    for (int st = 128; st > 0; st >>= 1) {
        if (tid < st) red[tid] += red[tid + st];
        __syncthreads();
    }
    if (tid == 0) {
        float total = red[0];
#pragma unroll
        for (int b = 0; b < 8; b++) total += batch_loss[b];
        out[0] = total;
    }
}

// ---------------------------------------------------------------------------
extern "C" void kernel_launch(void* const* d_in, const int* in_sizes, int n_in,
                              void* d_out, int out_size)
{
    const float* x       = (const float*)d_in[0];
    const float* w       = (const float*)d_in[1];
    const float* bias    = (const float*)d_in[2];
    const int*   targets = (const int*)d_in[3];
    const int*   src     = (const int*)d_in[4];
    const int*   tgt     = (const int*)d_in[5];
    float* out = (float*)d_out;

    fused_gemm_stats<<<ROWS / BM, 256>>>(x, w, bias, targets);
    finalize_kernel<<<1, 256>>>(targets, src, tgt, out);
}